// round 1
// baseline (speedup 1.0000x reference)
#include <cuda_runtime.h>
#include <cstdint>
#include <math.h>

#define DINL __device__ __forceinline__

// ---------------- problem sizes ----------------
constexpr int B_ = 32, S_ = 1024, D_ = 768;
constexpr int HALF = D_ / 2; // 384

// ---------------- scratch (static device globals; no allocation) ----------------
__device__ __align__(16) float g_Q[B_ * S_ * D_];
__device__ __align__(16) float g_K[B_ * S_ * D_];
__device__ __align__(16) float g_V[B_ * S_ * D_];
__device__ __align__(16) float g_S[B_ * S_ * S_];
__device__ __align__(16) float g_cosT[S_ * HALF];
__device__ __align__(16) float g_sinT[S_ * HALF];

// ---------------- GEMM tiling ----------------
constexpr int BM = 128, BN = 128, BK = 32;
constexpr int AStr = BK + 4;            // 36 u32 row stride (conflict-free frag loads)
constexpr int ABUF = BM * AStr;         // 4608 u32 per buffer
constexpr int BStrNN = BN + 8;          // 136 u32 row stride for NN B tiles
constexpr int BBUF_NN = BK * BStrNN;    // 4352 u32 per buffer

constexpr int SMEM_NT = 8 * ABUF * 4;                       // 147456 B
constexpr int SMEM_NN = (4 * ABUF + 4 * BBUF_NN) * 4;       // 143360 B

// ---------------- tf32 helpers ----------------
DINL uint32_t f2tf(float x) {
    uint32_t r;
    asm("cvt.rna.tf32.f32 %0, %1;" : "=r"(r) : "f"(x));
    return r;
}

DINL void mma8(float c[4], const uint32_t a[4], const uint32_t b[2]) {
    asm volatile(
        "mma.sync.aligned.m16n8k8.row.col.f32.tf32.tf32.f32 "
        "{%0,%1,%2,%3}, {%4,%5,%6,%7}, {%8,%9}, {%0,%1,%2,%3};\n"
        : "+f"(c[0]), "+f"(c[1]), "+f"(c[2]), "+f"(c[3])
        : "r"(a[0]), "r"(a[1]), "r"(a[2]), "r"(a[3]), "r"(b[0]), "r"(b[1]));
}

// ---------------- global -> reg tile loaders ----------------
// A-style tile (also B in NT mode): 128 rows x 32 cols, row-major source, ld = LD
template <int LD>
DINL void ldg_tileA(const float* __restrict__ base, int kt, float4* v, int tid) {
#pragma unroll
    for (int i = 0; i < 4; i++) {
        int f = tid + (i << 8);
        int r = f >> 3, c4 = f & 7;
        v[i] = *reinterpret_cast<const float4*>(base + (size_t)r * LD + kt * BK + (c4 << 2));
    }
}

// B tile in NN mode: 32 rows (k) x 128 cols (n), row-major source, ld = LD
template <int LD>
DINL void ldg_tileBnn(const float* __restrict__ base, int kt, float4* v, int tid) {
#pragma unroll
    for (int i = 0; i < 4; i++) {
        int f = tid + (i << 8);
        int r = f >> 5, c4 = f & 31;
        v[i] = *reinterpret_cast<const float4*>(base + (size_t)(kt * BK + r) * LD + (c4 << 2));
    }
}

// ---------------- reg -> smem stores with tf32 hi/lo split ----------------
DINL void split4(const float4& v, uint32_t h[4], uint32_t l[4]) {
    const float* pv = reinterpret_cast<const float*>(&v);
#pragma unroll
    for (int j = 0; j < 4; j++) {
        h[j] = f2tf(pv[j]);
        l[j] = f2tf(pv[j] - __uint_as_float(h[j]));
    }
}

DINL void sts_tileA(uint32_t* smH, uint32_t* smL, int buf, const float4* v, int tid) {
#pragma unroll
    for (int i = 0; i < 4; i++) {
        int f = tid + (i << 8);
        int r = f >> 3, c4 = f & 7;
        uint32_t h[4], l[4];
        split4(v[i], h, l);
        int off = buf * ABUF + r * AStr + (c4 << 2);
        *reinterpret_cast<uint4*>(smH + off) = make_uint4(h[0], h[1], h[2], h[3]);
        *reinterpret_cast<uint4*>(smL + off) = make_uint4(l[0], l[1], l[2], l[3]);
    }
}

DINL void sts_tileBnn(uint32_t* smH, uint32_t* smL, int buf, const float4* v, int tid) {
#pragma unroll
    for (int i = 0; i < 4; i++) {
        int f = tid + (i << 8);
        int r = f >> 5, c4 = f & 31;
        uint32_t h[4], l[4];
        split4(v[i], h, l);
        int off = buf * BBUF_NN + r * BStrNN + (c4 << 2);
        *reinterpret_cast<uint4*>(smH + off) = make_uint4(h[0], h[1], h[2], h[3]);
        *reinterpret_cast<uint4*>(smL + off) = make_uint4(l[0], l[1], l[2], l[3]);
    }
}

// ---------------- compute one 128x128x32 tile (3xTF32) ----------------
DINL void compute_tile_nt(const uint32_t* smAh, const uint32_t* smAl,
                          const uint32_t* smBh, const uint32_t* smBl,
                          int buf, float c[4][4][4]) {
    const int lane = threadIdx.x & 31, warp = threadIdx.x >> 5;
    const int wm = warp >> 2, wn = warp & 3, g = lane >> 2, tg = lane & 3;
    const int base = buf * ABUF;
#pragma unroll
    for (int kk = 0; kk < 4; kk++) {
        uint32_t ah[4][4], al[4][4];
#pragma unroll
        for (int mf = 0; mf < 4; mf++) {
            int o = base + (wm * 64 + mf * 16 + g) * AStr + kk * 8 + tg;
            int o8 = o + 8 * AStr;
            ah[mf][0] = smAh[o];      al[mf][0] = smAl[o];
            ah[mf][1] = smAh[o8];     al[mf][1] = smAl[o8];
            ah[mf][2] = smAh[o + 4];  al[mf][2] = smAl[o + 4];
            ah[mf][3] = smAh[o8 + 4]; al[mf][3] = smAl[o8 + 4];
        }
        uint32_t bh[4][2], bl[4][2];
#pragma unroll
        for (int nf = 0; nf < 4; nf++) {
            int o = base + (wn * 32 + nf * 8 + g) * AStr + kk * 8 + tg;
            bh[nf][0] = smBh[o]; bh[nf][1] = smBh[o + 4];
            bl[nf][0] = smBl[o]; bl[nf][1] = smBl[o + 4];
        }
#pragma unroll
        for (int mf = 0; mf < 4; mf++)
#pragma unroll
            for (int nf = 0; nf < 4; nf++) {
                mma8(c[mf][nf], ah[mf], bh[nf]);
                mma8(c[mf][nf], ah[mf], bl[nf]);
                mma8(c[mf][nf], al[mf], bh[nf]);
            }
    }
}

DINL void compute_tile_nn(const uint32_t* smAh, const uint32_t* smAl,
                          const uint32_t* smBh, const uint32_t* smBl,
                          int buf, float c[4][4][4]) {
    const int lane = threadIdx.x & 31, warp = threadIdx.x >> 5;
    const int wm = warp >> 2, wn = warp & 3, g = lane >> 2, tg = lane & 3;
    const int baseA = buf * ABUF;
    const int baseB = buf * BBUF_NN;
#pragma unroll
    for (int kk = 0; kk < 4; kk++) {
        uint32_t ah[4][4], al[4][4];
#pragma unroll
        for (int mf = 0; mf < 4; mf++) {
            int o = baseA + (wm * 64 + mf * 16 + g) * AStr + kk * 8 + tg;
            int o8 = o + 8 * AStr;
            ah[mf][0] = smAh[o];      al[mf][0] = smAl[o];
            ah[mf][1] = smAh[o8];     al[mf][1] = smAl[o8];
            ah[mf][2] = smAh[o + 4];  al[mf][2] = smAl[o + 4];
            ah[mf][3] = smAh[o8 + 4]; al[mf][3] = smAl[o8 + 4];
        }
        uint32_t bh[4][2], bl[4][2];
#pragma unroll
        for (int nf = 0; nf < 4; nf++) {
            int o = baseB + (kk * 8 + tg) * BStrNN + wn * 32 + nf * 8 + g;
            bh[nf][0] = smBh[o]; bh[nf][1] = smBh[o + 4 * BStrNN];
            bl[nf][0] = smBl[o]; bl[nf][1] = smBl[o + 4 * BStrNN];
        }
#pragma unroll
        for (int mf = 0; mf < 4; mf++)
#pragma unroll
            for (int nf = 0; nf < 4; nf++) {
                mma8(c[mf][nf], ah[mf], bh[nf]);
                mma8(c[mf][nf], ah[mf], bl[nf]);
                mma8(c[mf][nf], al[mf], bh[nf]);
            }
    }
}

// ---------------- full GEMM mainloop (double-buffered) ----------------
template <int KT, int LDA, int LDB, bool NT>
DINL void gemm_main(const float* __restrict__ Ab, const float* __restrict__ Bb,
                    uint32_t* sm, float c[4][4][4]) {
    const int tid = threadIdx.x;
    constexpr int BBUF = NT ? ABUF : BBUF_NN;
    uint32_t* Ah = sm;
    uint32_t* Al = sm + 2 * ABUF;
    uint32_t* Bh = sm + 4 * ABUF;
    uint32_t* Bl = Bh + 2 * BBUF;

#pragma unroll
    for (int mf = 0; mf < 4; mf++)
#pragma unroll
        for (int nf = 0; nf < 4; nf++)
#pragma unroll
            for (int r = 0; r < 4; r++) c[mf][nf][r] = 0.0f;

    float4 va[4], vb[4];
    ldg_tileA<LDA>(Ab, 0, va, tid);
    if (NT) ldg_tileA<LDB>(Bb, 0, vb, tid); else ldg_tileBnn<LDB>(Bb, 0, vb, tid);
    sts_tileA(Ah, Al, 0, va, tid);
    if (NT) sts_tileA(Bh, Bl, 0, vb, tid); else sts_tileBnn(Bh, Bl, 0, vb, tid);
    __syncthreads();

    for (int kt = 0; kt < KT; kt++) {
        int buf = kt & 1;
        if (kt + 1 < KT) {
            ldg_tileA<LDA>(Ab, kt + 1, va, tid);
            if (NT) ldg_tileA<LDB>(Bb, kt + 1, vb, tid); else ldg_tileBnn<LDB>(Bb, kt + 1, vb, tid);
        }
        if (NT) compute_tile_nt(Ah, Al, Bh, Bl, buf, c);
        else    compute_tile_nn(Ah, Al, Bh, Bl, buf, c);
        if (kt + 1 < KT) {
            sts_tileA(Ah, Al, buf ^ 1, va, tid);
            if (NT) sts_tileA(Bh, Bl, buf ^ 1, vb, tid); else sts_tileBnn(Bh, Bl, buf ^ 1, vb, tid);
        }
        __syncthreads();
    }
}

// ---------------- kernel 0: RoPE cos/sin tables ----------------
__global__ void k_ropetab() {
    int idx = blockIdx.x * 256 + threadIdx.x;
    if (idx >= S_ * HALF) return;
    int s = idx / HALF, i = idx - s * HALF;
    float e = (2.0f * (float)i) / 768.0f;          // matches reference fp32 arithmetic
    float invf = 1.0f / powf(10000.0f, e);
    float ang = (float)s * invf;
    float sn, cs;
    sincosf(ang, &sn, &cs);
    g_cosT[idx] = cs;
    g_sinT[idx] = sn;
}

// ---------------- kernel 1: QKV projection + bias + RoPE ----------------
__global__ void __launch_bounds__(256, 1)
k_qkv(const float* __restrict__ x,
      const float* __restrict__ Wq, const float* __restrict__ bq,
      const float* __restrict__ Wk, const float* __restrict__ bk,
      const float* __restrict__ Wv, const float* __restrict__ bv) {
    extern __shared__ uint32_t sm[];
    int z = blockIdx.z;
    const float* W  = (z == 0) ? Wq : (z == 1) ? Wk : Wv;
    const float* bb = (z == 0) ? bq : (z == 1) ? bk : bv;
    float* C        = (z == 0) ? g_Q : (z == 1) ? g_K : g_V;

    const float* Ab = x + (size_t)(blockIdx.y * BM) * D_;
    const float* Bb = W + (size_t)(blockIdx.x * BN) * D_;

    float c[4][4][4];
    gemm_main<24, D_, D_, true>(Ab, Bb, sm, c);

    const int lane = threadIdx.x & 31, warp = threadIdx.x >> 5;
    const int wm = warp >> 2, wn = warp & 3, g = lane >> 2, tg = lane & 3;
    const int bm = blockIdx.y * BM, bn = blockIdx.x * BN;
    const bool rope = (z < 2);
#pragma unroll
    for (int mf = 0; mf < 4; mf++) {
#pragma unroll
        for (int h = 0; h < 2; h++) {
            int r = bm + wm * 64 + mf * 16 + g + h * 8;
            int s = r & (S_ - 1);
#pragma unroll
            for (int nf = 0; nf < 4; nf++) {
                int col = bn + wn * 32 + nf * 8 + 2 * tg;
                float2 bia = *reinterpret_cast<const float2*>(bb + col);
                float v0 = c[mf][nf][h * 2 + 0] + bia.x;
                float v1 = c[mf][nf][h * 2 + 1] + bia.y;
                if (rope) {
                    int i = col >> 1;
                    float cs = g_cosT[s * HALF + i];
                    float sn = g_sinT[s * HALF + i];
                    float t0 = v0 * cs - v1 * sn;
                    v1 = v0 * sn + v1 * cs;
                    v0 = t0;
                }
                *reinterpret_cast<float2*>(C + (size_t)r * D_ + col) = make_float2(v0, v1);
            }
        }
    }
}

// ---------------- kernel 2: scores = Q K^T * scale ----------------
__global__ void __launch_bounds__(256, 1)
k_scores(float scale) {
    extern __shared__ uint32_t sm[];
    int z = blockIdx.z;
    const float* Ab = g_Q + (size_t)z * S_ * D_ + (size_t)(blockIdx.y * BM) * D_;
    const float* Bb = g_K + (size_t)z * S_ * D_ + (size_t)(blockIdx.x * BN) * D_;
    float* C = g_S + (size_t)z * S_ * S_;

    float c[4][4][4];
    gemm_main<24, D_, D_, true>(Ab, Bb, sm, c);

    const int lane = threadIdx.x & 31, warp = threadIdx.x >> 5;
    const int wm = warp >> 2, wn = warp & 3, g = lane >> 2, tg = lane & 3;
    const int bm = blockIdx.y * BM, bn = blockIdx.x * BN;
#pragma unroll
    for (int mf = 0; mf < 4; mf++) {
#pragma unroll
        for (int h = 0; h < 2; h++) {
            int r = bm + wm * 64 + mf * 16 + g + h * 8;
#pragma unroll
            for (int nf = 0; nf < 4; nf++) {
                int col = bn + wn * 32 + nf * 8 + 2 * tg;
                float v0 = c[mf][nf][h * 2 + 0] * scale;
                float v1 = c[mf][nf][h * 2 + 1] * scale;
                *reinterpret_cast<float2*>(C + (size_t)r * S_ + col) = make_float2(v0, v1);
            }
        }
    }
}

// ---------------- kernel 3: row softmax over 1024, in place ----------------
__global__ void __launch_bounds__(128)
k_softmax() {
    float* p = g_S + (size_t)blockIdx.x * S_;
    int t = threadIdx.x;
    float4 a = reinterpret_cast<float4*>(p)[t];
    float4 b = reinterpret_cast<float4*>(p)[t + 128];

    float m = fmaxf(fmaxf(fmaxf(a.x, a.y), fmaxf(a.z, a.w)),
                    fmaxf(fmaxf(b.x, b.y), fmaxf(b.z, b.w)));
#pragma unroll
    for (int o = 16; o > 0; o >>= 1) m = fmaxf(m, __shfl_xor_sync(0xffffffffu, m, o));
    __shared__ float r1[4], r2[4];
    if ((t & 31) == 0) r1[t >> 5] = m;
    __syncthreads();
    m = fmaxf(fmaxf(r1[0], r1[1]), fmaxf(r1[2], r1[3]));

    a.x = expf(a.x - m); a.y = expf(a.y - m); a.z = expf(a.z - m); a.w = expf(a.w - m);
    b.x = expf(b.x - m); b.y = expf(b.y - m); b.z = expf(b.z - m); b.w = expf(b.w - m);
    float s = a.x + a.y + a.z + a.w + b.x + b.y + b.z + b.w;
#pragma unroll
    for (int o = 16; o > 0; o >>= 1) s += __shfl_xor_sync(0xffffffffu, s, o);
    if ((t & 31) == 0) r2[t >> 5] = s;
    __syncthreads();
    s = r2[0] + r2[1] + r2[2] + r2[3];
    float inv = 1.0f / s;
    a.x *= inv; a.y *= inv; a.z *= inv; a.w *= inv;
    b.x *= inv; b.y *= inv; b.z *= inv; b.w *= inv;
    reinterpret_cast<float4*>(p)[t] = a;
    reinterpret_cast<float4*>(p)[t + 128] = b;
}

// ---------------- kernel 4: out = P V (NN GEMM) ----------------
__global__ void __launch_bounds__(256, 1)
k_pv(float* __restrict__ out) {
    extern __shared__ uint32_t sm[];
    int z = blockIdx.z;
    const float* Ab = g_S + (size_t)z * S_ * S_ + (size_t)(blockIdx.y * BM) * S_;
    const float* Bb = g_V + (size_t)z * S_ * D_ + blockIdx.x * BN;
    float* C = out + (size_t)z * S_ * D_;

    float c[4][4][4];
    gemm_main<32, S_, D_, false>(Ab, Bb, sm, c);

    const int lane = threadIdx.x & 31, warp = threadIdx.x >> 5;
    const int wm = warp >> 2, wn = warp & 3, g = lane >> 2, tg = lane & 3;
    const int bm = blockIdx.y * BM, bn = blockIdx.x * BN;
#pragma unroll
    for (int mf = 0; mf < 4; mf++) {
#pragma unroll
        for (int h = 0; h < 2; h++) {
            int r = bm + wm * 64 + mf * 16 + g + h * 8;
#pragma unroll
            for (int nf = 0; nf < 4; nf++) {
                int col = bn + wn * 32 + nf * 8 + 2 * tg;
                *reinterpret_cast<float2*>(C + (size_t)r * D_ + col) =
                    make_float2(c[mf][nf][h * 2 + 0], c[mf][nf][h * 2 + 1]);
            }
        }
    }
}

// ---------------- launch ----------------
extern "C" void kernel_launch(void* const* d_in, const int* in_sizes, int n_in,
                              void* d_out, int out_size) {
    const float* x  = (const float*)d_in[0];
    const float* Wq = (const float*)d_in[1];
    const float* bq = (const float*)d_in[2];
    const float* Wk = (const float*)d_in[3];
    const float* bk = (const float*)d_in[4];
    const float* Wv = (const float*)d_in[5];
    const float* bv = (const float*)d_in[6];
    float* out = (float*)d_out;

    cudaFuncSetAttribute(k_qkv,    cudaFuncAttributeMaxDynamicSharedMemorySize, SMEM_NT);
    cudaFuncSetAttribute(k_scores, cudaFuncAttributeMaxDynamicSharedMemorySize, SMEM_NT);
    cudaFuncSetAttribute(k_pv,     cudaFuncAttributeMaxDynamicSharedMemorySize, SMEM_NN);

    k_ropetab<<<(S_ * HALF + 255) / 256, 256>>>();
    k_qkv<<<dim3(D_ / BN, (B_ * S_) / BM, 3), 256, SMEM_NT>>>(x, Wq, bq, Wk, bk, Wv, bv);
    float scale = 1.0f / sqrtf(768.0f);
    k_scores<<<dim3(S_ / BN, S_ / BM, B_), 256, SMEM_NT>>>(scale);
    k_softmax<<<dim3(B_ * S_), 128>>>();
    k_pv<<<dim3(D_ / BN, S_ / BM, B_), 256, SMEM_NN>>>(out);
}

// round 2
// speedup vs baseline: 1.7405x; 1.7405x over previous
#include <cuda_runtime.h>
#include <cuda_bf16.h>
#include <cstdint>
#include <math.h>

#define DINL __device__ __forceinline__

// ---------------- problem sizes ----------------
constexpr int B_ = 32, S_ = 1024, D_ = 768;
constexpr int HALF = D_ / 2; // 384

// ---------------- scratch (static device globals; no allocation) ----------------
__device__ __align__(16) float g_Q[B_ * S_ * D_];
__device__ __align__(16) float g_K[B_ * S_ * D_];
__device__ __align__(16) float g_Vt[B_ * D_ * S_];   // V stored transposed: [b][d][s]
__device__ __align__(16) float g_S[B_ * S_ * S_];
__device__ __align__(16) float g_cosT[S_ * HALF];
__device__ __align__(16) float g_sinT[S_ * HALF];

// ---------------- GEMM tiling ----------------
// 128x128x32 CTA tile, 8 warps of 64x32, bf16x3 split (Ootomo) on m16n8k16.
constexpr int BM = 128, BN = 128, BK = 32;
constexpr int WK = BK / 2;              // 16 bf16x2 words per row
constexpr int WStr = WK + 4;            // 20-word padded stride: frag loads conflict-free
constexpr int ABUF_W = BM * WStr;       // 2560 words per buffer
constexpr int SMEM_SZ = 8 * ABUF_W * 4; // Ah,Al,Bh,Bl x double buffer = 81920 B

// ---------------- bf16 split helpers ----------------
DINL void split_pack(const float4& v, uint2& h, uint2& l) {
    uint32_t u0 = __float_as_uint(v.x), u1 = __float_as_uint(v.y);
    uint32_t u2 = __float_as_uint(v.z), u3 = __float_as_uint(v.w);
    // hi = truncate-to-bf16, packed pairwise (low half = even k)
    asm("prmt.b32 %0, %1, %2, 0x7632;" : "=r"(h.x) : "r"(u0), "r"(u1));
    asm("prmt.b32 %0, %1, %2, 0x7632;" : "=r"(h.y) : "r"(u2), "r"(u3));
    float l0 = v.x - __uint_as_float(u0 & 0xffff0000u);
    float l1 = v.y - __uint_as_float(u1 & 0xffff0000u);
    float l2 = v.z - __uint_as_float(u2 & 0xffff0000u);
    float l3 = v.w - __uint_as_float(u3 & 0xffff0000u);
    asm("cvt.rn.bf16x2.f32 %0, %1, %2;" : "=r"(l.x) : "f"(l1), "f"(l0));
    asm("cvt.rn.bf16x2.f32 %0, %1, %2;" : "=r"(l.y) : "f"(l3), "f"(l2));
}

DINL void mma16(float c[4], const uint32_t a[4], const uint32_t b[2]) {
    asm volatile(
        "mma.sync.aligned.m16n8k16.row.col.f32.bf16.bf16.f32 "
        "{%0,%1,%2,%3}, {%4,%5,%6,%7}, {%8,%9}, {%0,%1,%2,%3};\n"
        : "+f"(c[0]), "+f"(c[1]), "+f"(c[2]), "+f"(c[3])
        : "r"(a[0]), "r"(a[1]), "r"(a[2]), "r"(a[3]), "r"(b[0]), "r"(b[1]));
}

// ---------------- global -> reg tile loader (128 rows x 32 cols, row-major, ld=LD) ----------------
template <int LD>
DINL void ldg_tile(const float* __restrict__ base, int kt, float4* v, int tid) {
#pragma unroll
    for (int i = 0; i < 4; i++) {
        int f = tid + (i << 8);
        int r = f >> 3, c4 = f & 7;
        v[i] = *reinterpret_cast<const float4*>(base + (size_t)r * LD + kt * BK + (c4 << 2));
    }
}

// ---------------- reg -> smem store with bf16 hi/lo split ----------------
DINL void sts_tile(uint32_t* smH, uint32_t* smL, int buf, const float4* v, int tid) {
#pragma unroll
    for (int i = 0; i < 4; i++) {
        int f = tid + (i << 8);
        int r = f >> 3, c4 = f & 7;
        uint2 h, l;
        split_pack(v[i], h, l);
        int off = buf * ABUF_W + r * WStr + (c4 << 1);
        *reinterpret_cast<uint2*>(smH + off) = h;
        *reinterpret_cast<uint2*>(smL + off) = l;
    }
}

// ---------------- compute one 128x128x32 tile (bf16x3) ----------------
DINL void compute_tile(const uint32_t* smAh, const uint32_t* smAl,
                       const uint32_t* smBh, const uint32_t* smBl,
                       int buf, float c[4][4][4]) {
    const int lane = threadIdx.x & 31, warp = threadIdx.x >> 5;
    const int wm = warp >> 2, wn = warp & 3, g = lane >> 2, tg = lane & 3;
    const int base = buf * ABUF_W;
#pragma unroll
    for (int kk = 0; kk < 2; kk++) {
        uint32_t ah[4][4], al[4][4];
#pragma unroll
        for (int mf = 0; mf < 4; mf++) {
            int o = base + (wm * 64 + mf * 16 + g) * WStr + kk * 8 + tg;
            int o8 = o + 8 * WStr;
            ah[mf][0] = smAh[o];      al[mf][0] = smAl[o];
            ah[mf][1] = smAh[o8];     al[mf][1] = smAl[o8];
            ah[mf][2] = smAh[o + 4];  al[mf][2] = smAl[o + 4];
            ah[mf][3] = smAh[o8 + 4]; al[mf][3] = smAl[o8 + 4];
        }
        uint32_t bh[4][2], bl[4][2];
#pragma unroll
        for (int nf = 0; nf < 4; nf++) {
            int o = base + (wn * 32 + nf * 8 + g) * WStr + kk * 8 + tg;
            bh[nf][0] = smBh[o]; bh[nf][1] = smBh[o + 4];
            bl[nf][0] = smBl[o]; bl[nf][1] = smBl[o + 4];
        }
#pragma unroll
        for (int mf = 0; mf < 4; mf++)
#pragma unroll
            for (int nf = 0; nf < 4; nf++) {
                mma16(c[mf][nf], ah[mf], bh[nf]);
                mma16(c[mf][nf], ah[mf], bl[nf]);
                mma16(c[mf][nf], al[mf], bh[nf]);
            }
    }
}

// ---------------- full GEMM mainloop (double-buffered, NT) ----------------
template <int KT, int LDA, int LDB>
DINL void gemm_main(const float* __restrict__ Ab, const float* __restrict__ Bb,
                    uint32_t* sm, float c[4][4][4]) {
    const int tid = threadIdx.x;
    uint32_t* Ah = sm;
    uint32_t* Al = sm + 2 * ABUF_W;
    uint32_t* Bh = sm + 4 * ABUF_W;
    uint32_t* Bl = sm + 6 * ABUF_W;

#pragma unroll
    for (int mf = 0; mf < 4; mf++)
#pragma unroll
        for (int nf = 0; nf < 4; nf++)
#pragma unroll
            for (int r = 0; r < 4; r++) c[mf][nf][r] = 0.0f;

    float4 va[4], vb[4];
    ldg_tile<LDA>(Ab, 0, va, tid);
    ldg_tile<LDB>(Bb, 0, vb, tid);
    sts_tile(Ah, Al, 0, va, tid);
    sts_tile(Bh, Bl, 0, vb, tid);
    __syncthreads();

    for (int kt = 0; kt < KT; kt++) {
        int buf = kt & 1;
        if (kt + 1 < KT) {
            ldg_tile<LDA>(Ab, kt + 1, va, tid);
            ldg_tile<LDB>(Bb, kt + 1, vb, tid);
        }
        compute_tile(Ah, Al, Bh, Bl, buf, c);
        if (kt + 1 < KT) {
            sts_tile(Ah, Al, buf ^ 1, va, tid);
            sts_tile(Bh, Bl, buf ^ 1, vb, tid);
        }
        __syncthreads();
    }
}

// ---------------- kernel 0: RoPE cos/sin tables ----------------
__global__ void k_ropetab() {
    int idx = blockIdx.x * 256 + threadIdx.x;
    if (idx >= S_ * HALF) return;
    int s = idx / HALF, i = idx - s * HALF;
    float e = (2.0f * (float)i) / 768.0f;
    float invf = 1.0f / powf(10000.0f, e);
    float ang = (float)s * invf;
    float sn, cs;
    sincosf(ang, &sn, &cs);
    g_cosT[idx] = cs;
    g_sinT[idx] = sn;
}

// ---------------- kernel 1: QKV projection + bias + RoPE (+scale on Q, V transposed) ----------------
__global__ void __launch_bounds__(256, 1)
k_qkv(const float* __restrict__ x,
      const float* __restrict__ Wq, const float* __restrict__ bq,
      const float* __restrict__ Wk, const float* __restrict__ bk,
      const float* __restrict__ Wv, const float* __restrict__ bv) {
    extern __shared__ uint32_t sm[];
    int z = blockIdx.z;
    const float* W  = (z == 0) ? Wq : (z == 1) ? Wk : Wv;
    const float* bb = (z == 0) ? bq : (z == 1) ? bk : bv;

    const float* Ab = x + (size_t)(blockIdx.y * BM) * D_;
    const float* Bb = W + (size_t)(blockIdx.x * BN) * D_;

    float c[4][4][4];
    gemm_main<24, D_, D_>(Ab, Bb, sm, c);

    const int lane = threadIdx.x & 31, warp = threadIdx.x >> 5;
    const int wm = warp >> 2, wn = warp & 3, g = lane >> 2, tg = lane & 3;
    const int bm = blockIdx.y * BM, bn = blockIdx.x * BN;
    const float qscale = 0.03608439182435161f;  // 1/sqrt(768)
#pragma unroll
    for (int mf = 0; mf < 4; mf++) {
#pragma unroll
        for (int h = 0; h < 2; h++) {
            int r = bm + wm * 64 + mf * 16 + g + h * 8;
            int s = r & (S_ - 1);
            int b = r >> 10;
#pragma unroll
            for (int nf = 0; nf < 4; nf++) {
                int col = bn + wn * 32 + nf * 8 + 2 * tg;
                float2 bia = *reinterpret_cast<const float2*>(bb + col);
                float v0 = c[mf][nf][h * 2 + 0] + bia.x;
                float v1 = c[mf][nf][h * 2 + 1] + bia.y;
                if (z < 2) {
                    int i = col >> 1;
                    float cs = g_cosT[s * HALF + i];
                    float sn = g_sinT[s * HALF + i];
                    float t0 = v0 * cs - v1 * sn;
                    v1 = v0 * sn + v1 * cs;
                    v0 = t0;
                    if (z == 0) { v0 *= qscale; v1 *= qscale; }
                    float* C = (z == 0) ? g_Q : g_K;
                    *reinterpret_cast<float2*>(C + (size_t)r * D_ + col) = make_float2(v0, v1);
                } else {
                    // V: store transposed [b][d][s]
                    float* Ct = g_Vt + (size_t)b * D_ * S_;
                    Ct[(size_t)col * S_ + s] = v0;
                    Ct[(size_t)(col + 1) * S_ + s] = v1;
                }
            }
        }
    }
}

// ---------------- kernel 2: scores = (Q*scale) K^T ----------------
__global__ void __launch_bounds__(256, 1)
k_scores() {
    extern __shared__ uint32_t sm[];
    int z = blockIdx.z;
    const float* Ab = g_Q + (size_t)z * S_ * D_ + (size_t)(blockIdx.y * BM) * D_;
    const float* Bb = g_K + (size_t)z * S_ * D_ + (size_t)(blockIdx.x * BN) * D_;
    float* C = g_S + (size_t)z * S_ * S_;

    float c[4][4][4];
    gemm_main<24, D_, D_>(Ab, Bb, sm, c);

    const int lane = threadIdx.x & 31, warp = threadIdx.x >> 5;
    const int wm = warp >> 2, wn = warp & 3, g = lane >> 2, tg = lane & 3;
    const int bm = blockIdx.y * BM, bn = blockIdx.x * BN;
#pragma unroll
    for (int mf = 0; mf < 4; mf++) {
#pragma unroll
        for (int h = 0; h < 2; h++) {
            int r = bm + wm * 64 + mf * 16 + g + h * 8;
#pragma unroll
            for (int nf = 0; nf < 4; nf++) {
                int col = bn + wn * 32 + nf * 8 + 2 * tg;
                *reinterpret_cast<float2*>(C + (size_t)r * S_ + col) =
                    make_float2(c[mf][nf][h * 2 + 0], c[mf][nf][h * 2 + 1]);
            }
        }
    }
}

// ---------------- kernel 3: row softmax over 1024, in place ----------------
__global__ void __launch_bounds__(128)
k_softmax() {
    float* p = g_S + (size_t)blockIdx.x * S_;
    int t = threadIdx.x;
    float4 a = reinterpret_cast<float4*>(p)[t];
    float4 b = reinterpret_cast<float4*>(p)[t + 128];

    float m = fmaxf(fmaxf(fmaxf(a.x, a.y), fmaxf(a.z, a.w)),
                    fmaxf(fmaxf(b.x, b.y), fmaxf(b.z, b.w)));
#pragma unroll
    for (int o = 16; o > 0; o >>= 1) m = fmaxf(m, __shfl_xor_sync(0xffffffffu, m, o));
    __shared__ float r1[4], r2[4];
    if ((t & 31) == 0) r1[t >> 5] = m;
    __syncthreads();
    m = fmaxf(fmaxf(r1[0], r1[1]), fmaxf(r1[2], r1[3]));

    a.x = expf(a.x - m); a.y = expf(a.y - m); a.z = expf(a.z - m); a.w = expf(a.w - m);
    b.x = expf(b.x - m); b.y = expf(b.y - m); b.z = expf(b.z - m); b.w = expf(b.w - m);
    float s = a.x + a.y + a.z + a.w + b.x + b.y + b.z + b.w;
#pragma unroll
    for (int o = 16; o > 0; o >>= 1) s += __shfl_xor_sync(0xffffffffu, s, o);
    if ((t & 31) == 0) r2[t >> 5] = s;
    __syncthreads();
    s = r2[0] + r2[1] + r2[2] + r2[3];
    float inv = 1.0f / s;
    a.x *= inv; a.y *= inv; a.z *= inv; a.w *= inv;
    b.x *= inv; b.y *= inv; b.z *= inv; b.w *= inv;
    reinterpret_cast<float4*>(p)[t] = a;
    reinterpret_cast<float4*>(p)[t + 128] = b;
}

// ---------------- kernel 4: out = P V  (NT via transposed V) ----------------
__global__ void __launch_bounds__(256, 1)
k_pv(float* __restrict__ out) {
    extern __shared__ uint32_t sm[];
    int z = blockIdx.z;
    const float* Ab = g_S  + (size_t)z * S_ * S_ + (size_t)(blockIdx.y * BM) * S_;
    const float* Bb = g_Vt + (size_t)z * D_ * S_ + (size_t)(blockIdx.x * BN) * S_;
    float* C = out + (size_t)z * S_ * D_;

    float c[4][4][4];
    gemm_main<32, S_, S_>(Ab, Bb, sm, c);

    const int lane = threadIdx.x & 31, warp = threadIdx.x >> 5;
    const int wm = warp >> 2, wn = warp & 3, g = lane >> 2, tg = lane & 3;
    const int bm = blockIdx.y * BM, bn = blockIdx.x * BN;
#pragma unroll
    for (int mf = 0; mf < 4; mf++) {
#pragma unroll
        for (int h = 0; h < 2; h++) {
            int r = bm + wm * 64 + mf * 16 + g + h * 8;
#pragma unroll
            for (int nf = 0; nf < 4; nf++) {
                int col = bn + wn * 32 + nf * 8 + 2 * tg;
                *reinterpret_cast<float2*>(C + (size_t)r * D_ + col) =
                    make_float2(c[mf][nf][h * 2 + 0], c[mf][nf][h * 2 + 1]);
            }
        }
    }
}

// ---------------- launch ----------------
extern "C" void kernel_launch(void* const* d_in, const int* in_sizes, int n_in,
                              void* d_out, int out_size) {
    const float* x  = (const float*)d_in[0];
    const float* Wq = (const float*)d_in[1];
    const float* bq = (const float*)d_in[2];
    const float* Wk = (const float*)d_in[3];
    const float* bk = (const float*)d_in[4];
    const float* Wv = (const float*)d_in[5];
    const float* bv = (const float*)d_in[6];
    float* out = (float*)d_out;

    cudaFuncSetAttribute(k_qkv,    cudaFuncAttributeMaxDynamicSharedMemorySize, SMEM_SZ);
    cudaFuncSetAttribute(k_scores, cudaFuncAttributeMaxDynamicSharedMemorySize, SMEM_SZ);
    cudaFuncSetAttribute(k_pv,     cudaFuncAttributeMaxDynamicSharedMemorySize, SMEM_SZ);

    k_ropetab<<<(S_ * HALF + 255) / 256, 256>>>();
    k_qkv<<<dim3(D_ / BN, (B_ * S_) / BM, 3), 256, SMEM_SZ>>>(x, Wq, bq, Wk, bk, Wv, bv);
    k_scores<<<dim3(S_ / BN, S_ / BM, B_), 256, SMEM_SZ>>>();
    k_softmax<<<dim3(B_ * S_), 128>>>();
    k_pv<<<dim3(D_ / BN, S_ / BM, B_), 256, SMEM_SZ>>>(out);
}